// round 15
// baseline (speedup 1.0000x reference)
#include <cuda_runtime.h>
#include <cuda_fp16.h>

#define NMAX 100000
#define EMAX 1600000
#define NGRAPH 256
#define SCAN_B 256

// ---------------- static scratch (no allocation allowed) ----------------
__device__ int    g_degi[NMAX];
__device__ float  g_dinv[NMAX];
__device__ float  g_dinv2[NMAX];
__device__ int2   g_edge[EMAX];
__device__ int    g_rowptr[NMAX + 1];
__device__ int    g_tmp[NMAX];
__device__ int    g_partial[(NMAX + SCAN_B - 1) / SCAN_B + 1];
__device__ int    g_fill[NMAX];
__device__ float2 g_adj[EMAX];     // .x = src index bits, .y = norm weight
__device__ int    g_b32[NMAX];
__device__ __half g_xh[(size_t)NMAX * 64];    // fp16 input features
__device__ __half g_yh[(size_t)NMAX * 64];    // fp16 gather outputs (GEMM inputs)
__device__ __half g_th[(size_t)NMAX * 64];    // fp16 GEMM outputs (gather inputs)
__device__ __half g_h1h[(size_t)NMAX * 128];  // fp16 layer-1 activations
__device__ float  g_pool[NGRAPH * 32];
__device__ float  g_cnt[NGRAPH];
__device__ int    g_flag_ei;   // 1 = int64 data, 0 = int32 data
__device__ int    g_flag_b;

// ---------------- launch 1: zero + dtype-detect + x->fp16 ---------------
__global__ void k_prep0(int* degi, int* fill, float* pool, float* cnt, int n,
                        const long long* __restrict__ ei, int cnt_ei,
                        const long long* __restrict__ batch, long long start_b, int cnt_b,
                        int* flag_ei, int* flag_b,
                        const float4* __restrict__ X, __half2* __restrict__ Xh,
                        int ZB) {
    int bid = blockIdx.x;
    int tid = threadIdx.x;
    if (bid < 2) {
        const long long* p = bid ? batch : ei;
        long long start = bid ? start_b : 0;
        int count = bid ? cnt_b : cnt_ei;
        long long maxval = bid ? NGRAPH : n;
        int* flag = bid ? flag_b : flag_ei;
        __shared__ int bad;
        if (tid == 0) bad = 0;
        __syncthreads();
        for (int i = tid; i < count; i += blockDim.x) {
            long long v = p[start + i];
            if (v < 0 || v >= maxval) bad = 1;  // benign race
        }
        __syncthreads();
        if (tid == 0) *flag = bad ? 0 : 1;
    } else if (bid < 2 + ZB) {
        int i = (bid - 2) * 256 + tid;
        if (i < n) { degi[i] = 0; fill[i] = 0; }
        if (i < NGRAPH * 32) pool[i] = 0.f;
        if (i < NGRAPH) cnt[i] = 0.f;
    } else {
        int i = (bid - 2 - ZB) * 256 + tid;
        if (i < n * 16) {
            float4 v = __ldg(&X[i]);
            Xh[i * 2 + 0] = __floats2half2_rn(v.x, v.y);
            Xh[i * 2 + 1] = __floats2half2_rn(v.z, v.w);
        }
    }
}

// ---------------- launch 2: edge decode + degree ------------------------
__global__ void k_prep_edges(const void* __restrict__ ei, int2* __restrict__ edge,
                             int* degi, int E, int n, const int* __restrict__ flag) {
    int i = blockIdx.x * blockDim.x + threadIdx.x;
    if (i >= E) return;
    int s, d;
    if (*flag) {
        const long long* p = (const long long*)ei;
        s = (int)p[i];
        d = (int)p[(size_t)E + i];
    } else {
        const int* p = (const int*)ei;
        s = p[i];
        d = p[(size_t)E + i];
    }
    if ((unsigned)s >= (unsigned)n) s = 0;  // defensive: never trap
    if ((unsigned)d >= (unsigned)n) d = 0;
    edge[i] = make_int2(s, d);
    atomicAdd(&degi[d], 1);
}

// ---------------- launch 3: block scan + dinv ---------------------------
__global__ void k_scan1d(const int* __restrict__ degi, int* __restrict__ tmp,
                         int* __restrict__ partial, float* __restrict__ dinv,
                         float* __restrict__ dinv2, int n) {
    __shared__ int sh[SCAN_B];
    int t = threadIdx.x;
    int i = blockIdx.x * SCAN_B + t;
    int val = (i < n) ? degi[i] : 0;
    if (i < n) {
        float r = rsqrtf(1.0f + (float)val);
        dinv[i] = r;
        dinv2[i] = r * r;
    }
    sh[t] = val;
    __syncthreads();
    for (int off = 1; off < SCAN_B; off <<= 1) {
        int x = (t >= off) ? sh[t - off] : 0;
        __syncthreads();
        sh[t] += x;
        __syncthreads();
    }
    if (i < n) tmp[i] = sh[t] - val;              // exclusive within block
    if (t == SCAN_B - 1) partial[blockIdx.x] = sh[t];
}

__global__ void k_scan_part(int* partial, int nb) {
    __shared__ int sh[512];
    __shared__ int carry;
    int t = threadIdx.x;
    if (t == 0) carry = 0;
    __syncthreads();
    for (int base = 0; base < nb; base += 512) {
        int idx = base + t;
        int val = (idx < nb) ? partial[idx] : 0;
        sh[t] = val;
        __syncthreads();
        for (int off = 1; off < 512; off <<= 1) {
            int x = (t >= off) ? sh[t - off] : 0;
            __syncthreads();
            sh[t] += x;
            __syncthreads();
        }
        if (idx < nb) partial[idx] = sh[t] - val + carry;
        __syncthreads();
        if (t == 0) carry += sh[511];
        __syncthreads();
    }
}

// ---------------- launch 5: rowptr write + CSR fill + batch convert -----
// Fill blocks compute rowptr[d] inline (tmp+partial) so they don't depend
// on the rowptr-writer blocks (which exist for the gather kernels).
__global__ void k_fill_batch(const int2* __restrict__ edge, const int* __restrict__ tmp,
                             const int* __restrict__ partial, int* __restrict__ rowptr,
                             int* __restrict__ fill, const float* __restrict__ dinv,
                             float2* __restrict__ adj, int E, int FB,
                             const void* __restrict__ batch, int* __restrict__ b32,
                             int n, int BB, const int* __restrict__ flag_b) {
    int bid = blockIdx.x;
    int tid = threadIdx.x;
    if (bid < FB) {
        int i = bid * 256 + tid;
        if (i >= E) return;
        int2 ed = edge[i];
        int rp = tmp[ed.y] + partial[ed.y >> 8];   // SCAN_B == 256
        int pos = rp + atomicAdd(&fill[ed.y], 1);
        adj[pos] = make_float2(__int_as_float(ed.x), dinv[ed.x] * dinv[ed.y]);
    } else if (bid < FB + BB) {
        int i = (bid - FB) * 256 + tid;
        if (i >= n) return;
        int b = (*flag_b) ? (int)((const long long*)batch)[i] : ((const int*)batch)[i];
        if ((unsigned)b >= (unsigned)NGRAPH) b = 0;
        b32[i] = b;
    } else {
        int i = (bid - FB - BB) * 256 + tid;
        if (i < n) rowptr[i] = tmp[i] + partial[i >> 8];
        if (i == 0) rowptr[n] = E;
    }
}

// ---------------- quarter-warp CSR gather (F=64) ------------------------
// 4 edges in flight; each 8-lane group covers the 128B row with one uint4
// (8 fp16 features) per lane. One adj-LDG + one X-LDG serve FOUR edges.
__global__ void __launch_bounds__(256)
k_gather64q(const __half* __restrict__ X, __half* __restrict__ Y,
            const int* __restrict__ rowptr, const float2* __restrict__ adj,
            const float* __restrict__ dinv2, int n) {
    int warp = (blockIdx.x * 256 + threadIdx.x) >> 5;
    int lane = threadIdx.x & 31;
    int qw = lane >> 3;      // quarter id (edge offset 0-3)
    int ql = lane & 7;       // lane within quarter: features [8*ql, 8*ql+8)
    if (warp >= n) return;
    int start = __ldg(&rowptr[warp]);
    int end   = __ldg(&rowptr[warp + 1]);
    float a[8];
#pragma unroll
    for (int k = 0; k < 8; k++) a[k] = 0.f;
    if (qw == 0) {  // self-loop term on quarter 0 only
        float sw = __ldg(&dinv2[warp]);
        uint4 u = __ldg((const uint4*)(X + (size_t)warp * 64) + ql);
        float2 f0 = __half22float2(*(__half2*)&u.x);
        float2 f1 = __half22float2(*(__half2*)&u.y);
        float2 f2 = __half22float2(*(__half2*)&u.z);
        float2 f3 = __half22float2(*(__half2*)&u.w);
        a[0] = f0.x * sw; a[1] = f0.y * sw; a[2] = f1.x * sw; a[3] = f1.y * sw;
        a[4] = f2.x * sw; a[5] = f2.y * sw; a[6] = f3.x * sw; a[7] = f3.y * sw;
    }
    for (int i = start; i < end; i += 4) {
        int e = i + qw;
        if (e < end) {
            float2 ae = __ldg(&adj[e]);
            int src = __float_as_int(ae.x);
            float w = ae.y;
            uint4 u = __ldg((const uint4*)(X + (size_t)src * 64) + ql);
            float2 f0 = __half22float2(*(__half2*)&u.x);
            float2 f1 = __half22float2(*(__half2*)&u.y);
            float2 f2 = __half22float2(*(__half2*)&u.z);
            float2 f3 = __half22float2(*(__half2*)&u.w);
            a[0] += f0.x * w; a[1] += f0.y * w; a[2] += f1.x * w; a[3] += f1.y * w;
            a[4] += f2.x * w; a[5] += f2.y * w; a[6] += f3.x * w; a[7] += f3.y * w;
        }
    }
#pragma unroll
    for (int k = 0; k < 8; k++) {
        a[k] += __shfl_down_sync(0xffffffffu, a[k], 16);
        a[k] += __shfl_down_sync(0xffffffffu, a[k], 8);
    }
    if (qw == 0) {
        uint4 o;
        *(__half2*)&o.x = __floats2half2_rn(a[0], a[1]);
        *(__half2*)&o.y = __floats2half2_rn(a[2], a[3]);
        *(__half2*)&o.z = __floats2half2_rn(a[4], a[5]);
        *(__half2*)&o.w = __floats2half2_rn(a[6], a[7]);
        ((uint4*)(Y + (size_t)warp * 64))[ql] = o;
    }
}

// Paired-edge F=32 gather fused with bias+relu+mean-pool (R14-proven).
__global__ void __launch_bounds__(256)
k_gather32p_pool(const __half* __restrict__ X,
                 const int* __restrict__ rowptr, const float2* __restrict__ adj,
                 const float* __restrict__ dinv2, const int* __restrict__ batch,
                 const float* __restrict__ b4, float* __restrict__ pool,
                 float* __restrict__ cnt, int n) {
    int warp = (blockIdx.x * 256 + threadIdx.x) >> 5;
    int lane = threadIdx.x & 31;
    int hw = lane >> 4;
    int hl = lane & 15;
    if (warp >= n) return;
    int start = __ldg(&rowptr[warp]);
    int end   = __ldg(&rowptr[warp + 1]);
    float a0 = 0.f, a1 = 0.f;
    if (hw == 0) {
        float sw = __ldg(&dinv2[warp]);
        float2 f = __half22float2(__ldg((const __half2*)(X + (size_t)warp * 32) + hl));
        a0 = f.x * sw; a1 = f.y * sw;
    }
    for (int i = start; i < end; i += 2) {
        int e = i + hw;
        if (e < end) {
            float2 ae = __ldg(&adj[e]);
            int src = __float_as_int(ae.x);
            float w = ae.y;
            float2 f = __half22float2(__ldg((const __half2*)(X + (size_t)src * 32) + hl));
            a0 += f.x * w; a1 += f.y * w;
        }
    }
    a0 += __shfl_down_sync(0xffffffffu, a0, 16);
    a1 += __shfl_down_sync(0xffffffffu, a1, 16);
    if (hw == 0) {
        int b = __ldg(&batch[warp]);
        float v0 = fmaxf(a0 + __ldg(&b4[2 * hl]),     0.f);
        float v1 = fmaxf(a1 + __ldg(&b4[2 * hl + 1]), 0.f);
        atomicAdd(&pool[b * 32 + 2 * hl],     v0);
        atomicAdd(&pool[b * 32 + 2 * hl + 1], v1);
        if (hl == 0) atomicAdd(&cnt[b], 1.0f);
    }
}

// ---------------- tensor-core GEMM: fp16 A (exact), W = fp16 hi+lo ------
__device__ __forceinline__ void splith(float x0, float x1, unsigned& hi, unsigned& lo) {
    __half h0 = __float2half_rn(x0);
    __half h1 = __float2half_rn(x1);
    __half l0 = __float2half_rn(x0 - __half2float(h0));
    __half l1 = __float2half_rn(x1 - __half2float(h1));
    hi = (unsigned)__half_as_ushort(h0) | ((unsigned)__half_as_ushort(h1) << 16);
    lo = (unsigned)__half_as_ushort(l0) | ((unsigned)__half_as_ushort(l1) << 16);
}

__device__ __forceinline__ void mma16816h(float* c, const unsigned* a,
                                          unsigned b0, unsigned b1) {
    asm volatile("mma.sync.aligned.m16n8k16.row.col.f32.f16.f16.f32 "
                 "{%0,%1,%2,%3}, {%4,%5,%6,%7}, {%8,%9}, {%0,%1,%2,%3};"
                 : "+f"(c[0]), "+f"(c[1]), "+f"(c[2]), "+f"(c[3])
                 : "r"(a[0]), "r"(a[1]), "r"(a[2]), "r"(a[3]), "r"(b0), "r"(b1));
}

template <int KIN, int KOUT, bool INACT, bool OUTACT>
__global__ void __launch_bounds__(256)
k_gemm_tch(const __half2* __restrict__ X, const float* __restrict__ W,
           const float* __restrict__ bin, const float* __restrict__ bout,
           __half2* __restrict__ Y, int n) {
    constexpr int KS = KIN / 16;   // k-steps
    constexpr int NJ = KOUT / 8;   // n-tiles
    __shared__ uint4 Wp[KS * NJ * 32];    // (hi0,hi1,lo0,lo1) fragment-order
    __shared__ __half2 binh[KIN / 2];
    __shared__ float bouts[KOUT];
    int tid = threadIdx.x;
    int lane = tid & 31;
    int warp = tid >> 5;
    int g = lane >> 2;      // groupID (0-7)
    int tg = lane & 3;      // thread-in-group

    if (INACT)  for (int i = tid; i < KIN / 2; i += 256)
        binh[i] = __floats2half2_rn(bin[2 * i], bin[2 * i + 1]);
    if (OUTACT) for (int i = tid; i < KOUT; i += 256) bouts[i] = bout[i];

    for (int e = tid; e < KS * NJ * 32; e += 256) {
        int l  = e & 31;
        int j  = (e >> 5) % NJ;
        int ks = e / (32 * NJ);
        int col = j * 8 + (l >> 2);
        int k0  = ks * 16 + (l & 3) * 2;
        float w00 = W[(k0 + 0) * KOUT + col];
        float w01 = W[(k0 + 1) * KOUT + col];
        float w10 = W[(k0 + 8) * KOUT + col];
        float w11 = W[(k0 + 9) * KOUT + col];
        uint4 p;
        splith(w00, w01, p.x, p.z);
        splith(w10, w11, p.y, p.w);
        Wp[e] = p;
    }
    __syncthreads();

    int rowBase = blockIdx.x * 128 + warp * 16;
    int r0 = rowBase + g;
    int r1 = r0 + 8;
    bool v0 = (r0 < n), v1 = (r1 < n);
    const __half2* xr0 = X + (size_t)r0 * (KIN / 2);
    const __half2* xr1 = X + (size_t)r1 * (KIN / 2);
    const __half2 z2 = __floats2half2_rn(0.f, 0.f);

    unsigned a[KS * 4];
#pragma unroll
    for (int ks = 0; ks < KS; ks++) {
        int c2 = (ks * 16 + tg * 2) / 2;   // half2 index
        __half2 h00 = v0 ? xr0[c2]     : z2;
        __half2 h01 = v0 ? xr0[c2 + 4] : z2;
        __half2 h10 = v1 ? xr1[c2]     : z2;
        __half2 h11 = v1 ? xr1[c2 + 4] : z2;
        if (INACT) {
            h00 = __hmax2(__hadd2(h00, binh[c2]),     z2);
            h01 = __hmax2(__hadd2(h01, binh[c2 + 4]), z2);
            h10 = __hmax2(__hadd2(h10, binh[c2]),     z2);
            h11 = __hmax2(__hadd2(h11, binh[c2 + 4]), z2);
        }
        a[ks * 4 + 0] = *reinterpret_cast<unsigned*>(&h00);
        a[ks * 4 + 1] = *reinterpret_cast<unsigned*>(&h10);
        a[ks * 4 + 2] = *reinterpret_cast<unsigned*>(&h01);
        a[ks * 4 + 3] = *reinterpret_cast<unsigned*>(&h11);
    }

#pragma unroll
    for (int j = 0; j < NJ; j++) {
        float c[4] = {0.f, 0.f, 0.f, 0.f};
#pragma unroll
        for (int ks = 0; ks < KS; ks++) {
            uint4 wp = Wp[(ks * NJ + j) * 32 + lane];
            mma16816h(c, &a[ks * 4], wp.x, wp.y);   // A * Whi
            mma16816h(c, &a[ks * 4], wp.z, wp.w);   // A * Wlo
        }
        int col0 = j * 8 + tg * 2;
        if (OUTACT) {
            c[0] = fmaxf(c[0] + bouts[col0],     0.f);
            c[1] = fmaxf(c[1] + bouts[col0 + 1], 0.f);
            c[2] = fmaxf(c[2] + bouts[col0],     0.f);
            c[3] = fmaxf(c[3] + bouts[col0 + 1], 0.f);
        }
        if (v0) Y[((size_t)r0 * KOUT + col0) / 2] = __floats2half2_rn(c[0], c[1]);
        if (v1) Y[((size_t)r1 * KOUT + col0) / 2] = __floats2half2_rn(c[2], c[3]);
    }
}

// ---------------- final FC ----------------
__global__ void k_final(const float* __restrict__ pool, const float* __restrict__ cnt,
                        const float* __restrict__ Wfc, const float* __restrict__ bfc,
                        float* __restrict__ out) {
    int g = threadIdx.x;
    if (g >= NGRAPH) return;
    float s = 0.f;
#pragma unroll
    for (int f = 0; f < 32; f++) s += pool[g * 32 + f] * Wfc[f];
    out[g] = s / fmaxf(cnt[g], 1.0f) + bfc[0];
}

// ---------------- host ----------------
extern "C" void kernel_launch(void* const* d_in, const int* in_sizes, int n_in,
                              void* d_out, int out_size) {
    const float* x     = (const float*)d_in[0];
    const void*  ei    = d_in[1];
    const void*  batch = d_in[2];

    int base = -1;
    for (int i = 3; i + 9 < n_in; i++) {
        if (in_sizes[i] == 8192 && in_sizes[i + 1] == 128 &&
            in_sizes[i + 2] == 8192 && in_sizes[i + 3] == 64 &&
            in_sizes[i + 4] == 4096 && in_sizes[i + 5] == 64 &&
            in_sizes[i + 6] == 2048 && in_sizes[i + 7] == 32 &&
            in_sizes[i + 8] == 32 && in_sizes[i + 9] == 1) {
            base = i;
            break;
        }
    }
    if (base < 0) base = (n_in >= 14) ? 4 : 3;  // fallback

    const float* W1  = (const float*)d_in[base + 0];
    const float* b1  = (const float*)d_in[base + 1];
    const float* W2  = (const float*)d_in[base + 2];
    const float* b2  = (const float*)d_in[base + 3];
    const float* W3  = (const float*)d_in[base + 4];
    const float* b3  = (const float*)d_in[base + 5];
    const float* W4  = (const float*)d_in[base + 6];
    const float* b4  = (const float*)d_in[base + 7];
    const float* Wfc = (const float*)d_in[base + 8];
    const float* bfc = (const float*)d_in[base + 9];
    float* out = (float*)d_out;

    int n = in_sizes[0] / 64;
    int E = in_sizes[1] / 2;

    float *dinv, *dinv2, *pool, *cnt;
    __half *xh, *yh, *th, *h1h;
    float2* adj;
    int2* edge;
    int *degi, *rowptr, *tmp, *partial, *fill, *b32, *flag_ei, *flag_b;
    cudaGetSymbolAddress((void**)&degi,    g_degi);
    cudaGetSymbolAddress((void**)&dinv,    g_dinv);
    cudaGetSymbolAddress((void**)&dinv2,   g_dinv2);
    cudaGetSymbolAddress((void**)&edge,    g_edge);
    cudaGetSymbolAddress((void**)&rowptr,  g_rowptr);
    cudaGetSymbolAddress((void**)&tmp,     g_tmp);
    cudaGetSymbolAddress((void**)&partial, g_partial);
    cudaGetSymbolAddress((void**)&fill,    g_fill);
    cudaGetSymbolAddress((void**)&adj,     g_adj);
    cudaGetSymbolAddress((void**)&b32,     g_b32);
    cudaGetSymbolAddress((void**)&xh,      g_xh);
    cudaGetSymbolAddress((void**)&yh,      g_yh);
    cudaGetSymbolAddress((void**)&th,      g_th);
    cudaGetSymbolAddress((void**)&h1h,     g_h1h);
    cudaGetSymbolAddress((void**)&pool,    g_pool);
    cudaGetSymbolAddress((void**)&cnt,     g_cnt);
    cudaGetSymbolAddress((void**)&flag_ei, g_flag_ei);
    cudaGetSymbolAddress((void**)&flag_b,  g_flag_b);

    const int TB = 256;
    auto cdiv = [](long long a, long long b) { return (int)((a + b - 1) / b); };
    int nb = cdiv(n, SCAN_B);

    // ---- prep (5 launches) ----
    {
        int cnt_ei = (E / 2 < 4096) ? E / 2 : 4096;
        int cnt_b = (n / 2 < 4096) ? n / 2 : 4096;
        long long start_b = (long long)(n / 2) - cnt_b;
        int ZB = cdiv(n, TB);
        int CB = cdiv((long long)n * 16, TB);
        k_prep0<<<2 + ZB + CB, TB>>>(degi, fill, pool, cnt, n,
                                     (const long long*)ei, cnt_ei,
                                     (const long long*)batch, start_b, cnt_b,
                                     flag_ei, flag_b,
                                     (const float4*)x, (__half2*)xh, ZB);
    }
    k_prep_edges<<<cdiv(E, TB), TB>>>(ei, edge, degi, E, n, flag_ei);
    k_scan1d<<<nb, SCAN_B>>>(degi, tmp, partial, dinv, dinv2, n);
    k_scan_part<<<1, 512>>>(partial, nb);
    {
        int FB = cdiv(E, TB);
        int BB = cdiv(n, TB);
        int RB = cdiv(n + 1, TB);
        k_fill_batch<<<FB + BB + RB, TB>>>(edge, tmp, partial, rowptr, fill, dinv,
                                           adj, E, FB, batch, b32, n, BB, flag_b);
    }

    int gblocks = cdiv((long long)n * 32, TB);  // one warp per node
    int mblocks = cdiv(n, 128);                 // 128 rows per GEMM block

    // ---- layer 1: aggregate xh (64) -> yh, GEMM 64->128 (+b1+relu) -> h1h ----
    k_gather64q<<<gblocks, TB>>>(xh, yh, rowptr, adj, dinv2, n);
    k_gemm_tch<64, 128, false, true><<<mblocks, 256>>>((const __half2*)yh, W1, nullptr, b1, (__half2*)h1h, n);

    // ---- layer 2: GEMM 128->64 -> th, aggregate -> yh ----
    k_gemm_tch<128, 64, false, false><<<mblocks, 256>>>((const __half2*)h1h, W2, nullptr, nullptr, (__half2*)th, n);
    k_gather64q<<<gblocks, TB>>>(th, yh, rowptr, adj, dinv2, n);

    // ---- layer 3: relu(yh+b2) @ W3 (64->64) -> th, aggregate -> yh ----
    k_gemm_tch<64, 64, true, false><<<mblocks, 256>>>((const __half2*)yh, W3, b2, nullptr, (__half2*)th, n);
    k_gather64q<<<gblocks, TB>>>(th, yh, rowptr, adj, dinv2, n);

    // ---- layer 4: relu(yh+b3) @ W4 (64->32) -> th, fused gather+pool ----
    k_gemm_tch<64, 32, true, false><<<mblocks, 256>>>((const __half2*)yh, W4, b3, nullptr, (__half2*)th, n);
    k_gather32p_pool<<<gblocks, TB>>>(th, rowptr, adj, dinv2, b32, b4, pool, cnt, n);

    // ---- final FC ----
    k_final<<<1, 256>>>(pool, cnt, Wfc, bfc, out);
}

// round 16
// speedup vs baseline: 1.0127x; 1.0127x over previous
#include <cuda_runtime.h>
#include <cuda_fp16.h>

#define NMAX 100000
#define EMAX 1600000
#define NGRAPH 256
#define SCAN_B 256

// ---------------- static scratch (no allocation allowed) ----------------
__device__ int    g_degi[NMAX];
__device__ float  g_dinv[NMAX];
__device__ float  g_dinv2[NMAX];
__device__ int2   g_edge[EMAX];
__device__ int    g_rowptr[NMAX + 1];
__device__ int    g_tmp[NMAX];
__device__ int    g_partial[(NMAX + SCAN_B - 1) / SCAN_B + 1];
__device__ int    g_fill[NMAX];
__device__ float2 g_adj[EMAX];     // .x = src index bits, .y = norm weight
__device__ int    g_b32[NMAX];
__device__ __half g_xh[(size_t)NMAX * 64];    // fp16 input features
__device__ __half g_yh[(size_t)NMAX * 64];    // fp16 gather outputs (GEMM inputs)
__device__ __half g_th[(size_t)NMAX * 64];    // fp16 GEMM outputs (gather inputs)
__device__ __half g_h1h[(size_t)NMAX * 128];  // fp16 layer-1 activations
__device__ float  g_pool[NGRAPH * 32];
__device__ float  g_cnt[NGRAPH];
__device__ int    g_flag_ei;   // 1 = int64 data, 0 = int32 data
__device__ int    g_flag_b;

// ---------------- launch 1: zero + dtype-detect + x->fp16 ---------------
__global__ void k_prep0(int* degi, int* fill, float* pool, float* cnt, int n,
                        const long long* __restrict__ ei, int cnt_ei,
                        const long long* __restrict__ batch, long long start_b, int cnt_b,
                        int* flag_ei, int* flag_b,
                        const float4* __restrict__ X, __half2* __restrict__ Xh,
                        int ZB) {
    int bid = blockIdx.x;
    int tid = threadIdx.x;
    if (bid < 2) {
        const long long* p = bid ? batch : ei;
        long long start = bid ? start_b : 0;
        int count = bid ? cnt_b : cnt_ei;
        long long maxval = bid ? NGRAPH : n;
        int* flag = bid ? flag_b : flag_ei;
        __shared__ int bad;
        if (tid == 0) bad = 0;
        __syncthreads();
        for (int i = tid; i < count; i += blockDim.x) {
            long long v = p[start + i];
            if (v < 0 || v >= maxval) bad = 1;  // benign race
        }
        __syncthreads();
        if (tid == 0) *flag = bad ? 0 : 1;
    } else if (bid < 2 + ZB) {
        int i = (bid - 2) * 256 + tid;
        if (i < n) { degi[i] = 0; fill[i] = 0; }
        if (i < NGRAPH * 32) pool[i] = 0.f;
        if (i < NGRAPH) cnt[i] = 0.f;
    } else {
        int i = (bid - 2 - ZB) * 256 + tid;
        if (i < n * 16) {
            float4 v = __ldg(&X[i]);
            Xh[i * 2 + 0] = __floats2half2_rn(v.x, v.y);
            Xh[i * 2 + 1] = __floats2half2_rn(v.z, v.w);
        }
    }
}

// ---------------- launch 2: edge decode + degree ------------------------
__global__ void k_prep_edges(const void* __restrict__ ei, int2* __restrict__ edge,
                             int* degi, int E, int n, const int* __restrict__ flag) {
    int i = blockIdx.x * blockDim.x + threadIdx.x;
    if (i >= E) return;
    int s, d;
    if (*flag) {
        const long long* p = (const long long*)ei;
        s = (int)p[i];
        d = (int)p[(size_t)E + i];
    } else {
        const int* p = (const int*)ei;
        s = p[i];
        d = p[(size_t)E + i];
    }
    if ((unsigned)s >= (unsigned)n) s = 0;  // defensive: never trap
    if ((unsigned)d >= (unsigned)n) d = 0;
    edge[i] = make_int2(s, d);
    atomicAdd(&degi[d], 1);
}

// ---------------- launch 3: block scan + dinv ---------------------------
__global__ void k_scan1d(const int* __restrict__ degi, int* __restrict__ tmp,
                         int* __restrict__ partial, float* __restrict__ dinv,
                         float* __restrict__ dinv2, int n) {
    __shared__ int sh[SCAN_B];
    int t = threadIdx.x;
    int i = blockIdx.x * SCAN_B + t;
    int val = (i < n) ? degi[i] : 0;
    if (i < n) {
        float r = rsqrtf(1.0f + (float)val);
        dinv[i] = r;
        dinv2[i] = r * r;
    }
    sh[t] = val;
    __syncthreads();
    for (int off = 1; off < SCAN_B; off <<= 1) {
        int x = (t >= off) ? sh[t - off] : 0;
        __syncthreads();
        sh[t] += x;
        __syncthreads();
    }
    if (i < n) tmp[i] = sh[t] - val;              // exclusive within block
    if (t == SCAN_B - 1) partial[blockIdx.x] = sh[t];
}

__global__ void k_scan_part(int* partial, int nb) {
    __shared__ int sh[512];
    __shared__ int carry;
    int t = threadIdx.x;
    if (t == 0) carry = 0;
    __syncthreads();
    for (int base = 0; base < nb; base += 512) {
        int idx = base + t;
        int val = (idx < nb) ? partial[idx] : 0;
        sh[t] = val;
        __syncthreads();
        for (int off = 1; off < 512; off <<= 1) {
            int x = (t >= off) ? sh[t - off] : 0;
            __syncthreads();
            sh[t] += x;
            __syncthreads();
        }
        if (idx < nb) partial[idx] = sh[t] - val + carry;
        __syncthreads();
        if (t == 0) carry += sh[511];
        __syncthreads();
    }
}

// ---------------- launch 5: rowptr write + CSR fill + batch convert -----
__global__ void k_fill_batch(const int2* __restrict__ edge, const int* __restrict__ tmp,
                             const int* __restrict__ partial, int* __restrict__ rowptr,
                             int* __restrict__ fill, const float* __restrict__ dinv,
                             float2* __restrict__ adj, int E, int FB,
                             const void* __restrict__ batch, int* __restrict__ b32,
                             int n, int BB, const int* __restrict__ flag_b) {
    int bid = blockIdx.x;
    int tid = threadIdx.x;
    if (bid < FB) {
        int i = bid * 256 + tid;
        if (i >= E) return;
        int2 ed = edge[i];
        int rp = tmp[ed.y] + partial[ed.y >> 8];   // SCAN_B == 256
        int pos = rp + atomicAdd(&fill[ed.y], 1);
        adj[pos] = make_float2(__int_as_float(ed.x), dinv[ed.x] * dinv[ed.y]);
    } else if (bid < FB + BB) {
        int i = (bid - FB) * 256 + tid;
        if (i >= n) return;
        int b = (*flag_b) ? (int)((const long long*)batch)[i] : ((const int*)batch)[i];
        if ((unsigned)b >= (unsigned)NGRAPH) b = 0;
        b32[i] = b;
    } else {
        int i = (bid - FB - BB) * 256 + tid;
        if (i < n) rowptr[i] = tmp[i] + partial[i >> 8];
        if (i == 0) rowptr[n] = E;
    }
}

// ---------------- paired-edge CSR gather (F=64, R14-proven) -------------
__global__ void __launch_bounds__(512)
k_gather64p(const __half* __restrict__ X, __half* __restrict__ Y,
            const int* __restrict__ rowptr, const float2* __restrict__ adj,
            const float* __restrict__ dinv2, int n) {
    int warp = (blockIdx.x * 512 + threadIdx.x) >> 5;
    int lane = threadIdx.x & 31;
    int hw = lane >> 4;      // half-warp id (edge parity)
    int hl = lane & 15;      // lane within half: features [4*hl, 4*hl+4)
    if (warp >= n) return;
    int start = __ldg(&rowptr[warp]);
    int end   = __ldg(&rowptr[warp + 1]);
    float a0 = 0.f, a1 = 0.f, a2 = 0.f, a3 = 0.f;
    if (hw == 0) {  // self-loop term on low half only
        float sw = __ldg(&dinv2[warp]);
        uint2 u = __ldg((const uint2*)(X + (size_t)warp * 64) + hl);
        float2 fa = __half22float2(*(__half2*)&u.x);
        float2 fb = __half22float2(*(__half2*)&u.y);
        a0 = fa.x * sw; a1 = fa.y * sw; a2 = fb.x * sw; a3 = fb.y * sw;
    }
    for (int i = start; i < end; i += 2) {
        int e = i + hw;
        if (e < end) {
            float2 ae = __ldg(&adj[e]);
            int src = __float_as_int(ae.x);
            float w = ae.y;
            uint2 u = __ldg((const uint2*)(X + (size_t)src * 64) + hl);
            float2 fa = __half22float2(*(__half2*)&u.x);
            float2 fb = __half22float2(*(__half2*)&u.y);
            a0 += fa.x * w; a1 += fa.y * w; a2 += fb.x * w; a3 += fb.y * w;
        }
    }
    a0 += __shfl_down_sync(0xffffffffu, a0, 16);
    a1 += __shfl_down_sync(0xffffffffu, a1, 16);
    a2 += __shfl_down_sync(0xffffffffu, a2, 16);
    a3 += __shfl_down_sync(0xffffffffu, a3, 16);
    if (hw == 0) {
        uint2 o;
        *(__half2*)&o.x = __floats2half2_rn(a0, a1);
        *(__half2*)&o.y = __floats2half2_rn(a2, a3);
        ((uint2*)(Y + (size_t)warp * 64))[hl] = o;
    }
}

// Paired-edge F=32 gather fused with bias+relu+mean-pool (R14-proven).
__global__ void __launch_bounds__(512)
k_gather32p_pool(const __half* __restrict__ X,
                 const int* __restrict__ rowptr, const float2* __restrict__ adj,
                 const float* __restrict__ dinv2, const int* __restrict__ batch,
                 const float* __restrict__ b4, float* __restrict__ pool,
                 float* __restrict__ cnt, int n) {
    int warp = (blockIdx.x * 512 + threadIdx.x) >> 5;
    int lane = threadIdx.x & 31;
    int hw = lane >> 4;
    int hl = lane & 15;
    if (warp >= n) return;
    int start = __ldg(&rowptr[warp]);
    int end   = __ldg(&rowptr[warp + 1]);
    float a0 = 0.f, a1 = 0.f;
    if (hw == 0) {
        float sw = __ldg(&dinv2[warp]);
        float2 f = __half22float2(__ldg((const __half2*)(X + (size_t)warp * 32) + hl));
        a0 = f.x * sw; a1 = f.y * sw;
    }
    for (int i = start; i < end; i += 2) {
        int e = i + hw;
        if (e < end) {
            float2 ae = __ldg(&adj[e]);
            int src = __float_as_int(ae.x);
            float w = ae.y;
            float2 f = __half22float2(__ldg((const __half2*)(X + (size_t)src * 32) + hl));
            a0 += f.x * w; a1 += f.y * w;
        }
    }
    a0 += __shfl_down_sync(0xffffffffu, a0, 16);
    a1 += __shfl_down_sync(0xffffffffu, a1, 16);
    if (hw == 0) {
        int b = __ldg(&batch[warp]);
        float v0 = fmaxf(a0 + __ldg(&b4[2 * hl]),     0.f);
        float v1 = fmaxf(a1 + __ldg(&b4[2 * hl + 1]), 0.f);
        atomicAdd(&pool[b * 32 + 2 * hl],     v0);
        atomicAdd(&pool[b * 32 + 2 * hl + 1], v1);
        if (hl == 0) atomicAdd(&cnt[b], 1.0f);
    }
}

// ---------------- tensor-core GEMM: fp16 A (exact), W = fp16 hi+lo ------
__device__ __forceinline__ void splith(float x0, float x1, unsigned& hi, unsigned& lo) {
    __half h0 = __float2half_rn(x0);
    __half h1 = __float2half_rn(x1);
    __half l0 = __float2half_rn(x0 - __half2float(h0));
    __half l1 = __float2half_rn(x1 - __half2float(h1));
    hi = (unsigned)__half_as_ushort(h0) | ((unsigned)__half_as_ushort(h1) << 16);
    lo = (unsigned)__half_as_ushort(l0) | ((unsigned)__half_as_ushort(l1) << 16);
}

__device__ __forceinline__ void mma16816h(float* c, const unsigned* a,
                                          unsigned b0, unsigned b1) {
    asm volatile("mma.sync.aligned.m16n8k16.row.col.f32.f16.f16.f32 "
                 "{%0,%1,%2,%3}, {%4,%5,%6,%7}, {%8,%9}, {%0,%1,%2,%3};"
                 : "+f"(c[0]), "+f"(c[1]), "+f"(c[2]), "+f"(c[3])
                 : "r"(a[0]), "r"(a[1]), "r"(a[2]), "r"(a[3]), "r"(b0), "r"(b1));
}

template <int KIN, int KOUT, bool INACT, bool OUTACT>
__global__ void __launch_bounds__(256)
k_gemm_tch(const __half2* __restrict__ X, const float* __restrict__ W,
           const float* __restrict__ bin, const float* __restrict__ bout,
           __half2* __restrict__ Y, int n) {
    constexpr int KS = KIN / 16;   // k-steps
    constexpr int NJ = KOUT / 8;   // n-tiles
    __shared__ uint4 Wp[KS * NJ * 32];    // (hi0,hi1,lo0,lo1) fragment-order
    __shared__ __half2 binh[KIN / 2];
    __shared__ float bouts[KOUT];
    int tid = threadIdx.x;
    int lane = tid & 31;
    int warp = tid >> 5;
    int g = lane >> 2;      // groupID (0-7)
    int tg = lane & 3;      // thread-in-group

    if (INACT)  for (int i = tid; i < KIN / 2; i += 256)
        binh[i] = __floats2half2_rn(bin[2 * i], bin[2 * i + 1]);
    if (OUTACT) for (int i = tid; i < KOUT; i += 256) bouts[i] = bout[i];

    for (int e = tid; e < KS * NJ * 32; e += 256) {
        int l  = e & 31;
        int j  = (e >> 5) % NJ;
        int ks = e / (32 * NJ);
        int col = j * 8 + (l >> 2);
        int k0  = ks * 16 + (l & 3) * 2;
        float w00 = W[(k0 + 0) * KOUT + col];
        float w01 = W[(k0 + 1) * KOUT + col];
        float w10 = W[(k0 + 8) * KOUT + col];
        float w11 = W[(k0 + 9) * KOUT + col];
        uint4 p;
        splith(w00, w01, p.x, p.z);
        splith(w10, w11, p.y, p.w);
        Wp[e] = p;
    }
    __syncthreads();

    int rowBase = blockIdx.x * 128 + warp * 16;
    int r0 = rowBase + g;
    int r1 = r0 + 8;
    bool v0 = (r0 < n), v1 = (r1 < n);
    const __half2* xr0 = X + (size_t)r0 * (KIN / 2);
    const __half2* xr1 = X + (size_t)r1 * (KIN / 2);
    const __half2 z2 = __floats2half2_rn(0.f, 0.f);

    unsigned a[KS * 4];
#pragma unroll
    for (int ks = 0; ks < KS; ks++) {
        int c2 = (ks * 16 + tg * 2) / 2;   // half2 index
        __half2 h00 = v0 ? xr0[c2]     : z2;
        __half2 h01 = v0 ? xr0[c2 + 4] : z2;
        __half2 h10 = v1 ? xr1[c2]     : z2;
        __half2 h11 = v1 ? xr1[c2 + 4] : z2;
        if (INACT) {
            h00 = __hmax2(__hadd2(h00, binh[c2]),     z2);
            h01 = __hmax2(__hadd2(h01, binh[c2 + 4]), z2);
            h10 = __hmax2(__hadd2(h10, binh[c2]),     z2);
            h11 = __hmax2(__hadd2(h11, binh[c2 + 4]), z2);
        }
        a[ks * 4 + 0] = *reinterpret_cast<unsigned*>(&h00);
        a[ks * 4 + 1] = *reinterpret_cast<unsigned*>(&h10);
        a[ks * 4 + 2] = *reinterpret_cast<unsigned*>(&h01);
        a[ks * 4 + 3] = *reinterpret_cast<unsigned*>(&h11);
    }

#pragma unroll
    for (int j = 0; j < NJ; j++) {
        float c[4] = {0.f, 0.f, 0.f, 0.f};
#pragma unroll
        for (int ks = 0; ks < KS; ks++) {
            uint4 wp = Wp[(ks * NJ + j) * 32 + lane];
            mma16816h(c, &a[ks * 4], wp.x, wp.y);   // A * Whi
            mma16816h(c, &a[ks * 4], wp.z, wp.w);   // A * Wlo
        }
        int col0 = j * 8 + tg * 2;
        if (OUTACT) {
            c[0] = fmaxf(c[0] + bouts[col0],     0.f);
            c[1] = fmaxf(c[1] + bouts[col0 + 1], 0.f);
            c[2] = fmaxf(c[2] + bouts[col0],     0.f);
            c[3] = fmaxf(c[3] + bouts[col0 + 1], 0.f);
        }
        if (v0) Y[((size_t)r0 * KOUT + col0) / 2] = __floats2half2_rn(c[0], c[1]);
        if (v1) Y[((size_t)r1 * KOUT + col0) / 2] = __floats2half2_rn(c[2], c[3]);
    }
}

// ---------------- final FC ----------------
__global__ void k_final(const float* __restrict__ pool, const float* __restrict__ cnt,
                        const float* __restrict__ Wfc, const float* __restrict__ bfc,
                        float* __restrict__ out) {
    int g = threadIdx.x;
    if (g >= NGRAPH) return;
    float s = 0.f;
#pragma unroll
    for (int f = 0; f < 32; f++) s += pool[g * 32 + f] * Wfc[f];
    out[g] = s / fmaxf(cnt[g], 1.0f) + bfc[0];
}

// ---------------- host ----------------
extern "C" void kernel_launch(void* const* d_in, const int* in_sizes, int n_in,
                              void* d_out, int out_size) {
    const float* x     = (const float*)d_in[0];
    const void*  ei    = d_in[1];
    const void*  batch = d_in[2];

    int base = -1;
    for (int i = 3; i + 9 < n_in; i++) {
        if (in_sizes[i] == 8192 && in_sizes[i + 1] == 128 &&
            in_sizes[i + 2] == 8192 && in_sizes[i + 3] == 64 &&
            in_sizes[i + 4] == 4096 && in_sizes[i + 5] == 64 &&
            in_sizes[i + 6] == 2048 && in_sizes[i + 7] == 32 &&
            in_sizes[i + 8] == 32 && in_sizes[i + 9] == 1) {
            base = i;
            break;
        }
    }
    if (base < 0) base = (n_in >= 14) ? 4 : 3;  // fallback

    const float* W1  = (const float*)d_in[base + 0];
    const float* b1  = (const float*)d_in[base + 1];
    const float* W2  = (const float*)d_in[base + 2];
    const float* b2  = (const float*)d_in[base + 3];
    const float* W3  = (const float*)d_in[base + 4];
    const float* b3  = (const float*)d_in[base + 5];
    const float* W4  = (const float*)d_in[base + 6];
    const float* b4  = (const float*)d_in[base + 7];
    const float* Wfc = (const float*)d_in[base + 8];
    const float* bfc = (const float*)d_in[base + 9];
    float* out = (float*)d_out;

    int n = in_sizes[0] / 64;
    int E = in_sizes[1] / 2;

    float *dinv, *dinv2, *pool, *cnt;
    __half *xh, *yh, *th, *h1h;
    float2* adj;
    int2* edge;
    int *degi, *rowptr, *tmp, *partial, *fill, *b32, *flag_ei, *flag_b;
    cudaGetSymbolAddress((void**)&degi,    g_degi);
    cudaGetSymbolAddress((void**)&dinv,    g_dinv);
    cudaGetSymbolAddress((void**)&dinv2,   g_dinv2);
    cudaGetSymbolAddress((void**)&edge,    g_edge);
    cudaGetSymbolAddress((void**)&rowptr,  g_rowptr);
    cudaGetSymbolAddress((void**)&tmp,     g_tmp);
    cudaGetSymbolAddress((void**)&partial, g_partial);
    cudaGetSymbolAddress((void**)&fill,    g_fill);
    cudaGetSymbolAddress((void**)&adj,     g_adj);
    cudaGetSymbolAddress((void**)&b32,     g_b32);
    cudaGetSymbolAddress((void**)&xh,      g_xh);
    cudaGetSymbolAddress((void**)&yh,      g_yh);
    cudaGetSymbolAddress((void**)&th,      g_th);
    cudaGetSymbolAddress((void**)&h1h,     g_h1h);
    cudaGetSymbolAddress((void**)&pool,    g_pool);
    cudaGetSymbolAddress((void**)&cnt,     g_cnt);
    cudaGetSymbolAddress((void**)&flag_ei, g_flag_ei);
    cudaGetSymbolAddress((void**)&flag_b,  g_flag_b);

    const int TB = 256;
    auto cdiv = [](long long a, long long b) { return (int)((a + b - 1) / b); };
    int nb = cdiv(n, SCAN_B);

    // ---- prep (5 launches) ----
    {
        int cnt_ei = (E / 2 < 4096) ? E / 2 : 4096;
        int cnt_b = (n / 2 < 4096) ? n / 2 : 4096;
        long long start_b = (long long)(n / 2) - cnt_b;
        int ZB = cdiv(n, TB);
        int CB = cdiv((long long)n * 16, TB);
        k_prep0<<<2 + ZB + CB, TB>>>(degi, fill, pool, cnt, n,
                                     (const long long*)ei, cnt_ei,
                                     (const long long*)batch, start_b, cnt_b,
                                     flag_ei, flag_b,
                                     (const float4*)x, (__half2*)xh, ZB);
    }
    k_prep_edges<<<cdiv(E, TB), TB>>>(ei, edge, degi, E, n, flag_ei);
    k_scan1d<<<nb, SCAN_B>>>(degi, tmp, partial, dinv, dinv2, n);
    k_scan_part<<<1, 512>>>(partial, nb);
    {
        int FB = cdiv(E, TB);
        int BB = cdiv(n, TB);
        int RB = cdiv(n + 1, TB);
        k_fill_batch<<<FB + BB + RB, TB>>>(edge, tmp, partial, rowptr, fill, dinv,
                                           adj, E, FB, batch, b32, n, BB, flag_b);
    }

    int gblocks = cdiv((long long)n * 32, 512);  // one warp per node, 512-thr blocks
    int mblocks = cdiv(n, 128);                  // 128 rows per GEMM block

    // ---- layer 1: aggregate xh (64) -> yh, GEMM 64->128 (+b1+relu) -> h1h ----
    k_gather64p<<<gblocks, 512>>>(xh, yh, rowptr, adj, dinv2, n);
    k_gemm_tch<64, 128, false, true><<<mblocks, 256>>>((const __half2*)yh, W1, nullptr, b1, (__half2*)h1h, n);

    // ---- layer 2: GEMM 128->64 -> th, aggregate -> yh ----
    k_gemm_tch<128, 64, false, false><<<mblocks, 256>>>((const __half2*)h1h, W2, nullptr, nullptr, (__half2*)th, n);
    k_gather64p<<<gblocks, 512>>>(th, yh, rowptr, adj, dinv2, n);

    // ---- layer 3: relu(yh+b2) @ W3 (64->64) -> th, aggregate -> yh ----
    k_gemm_tch<64, 64, true, false><<<mblocks, 256>>>((const __half2*)yh, W3, b2, nullptr, (__half2*)th, n);
    k_gather64p<<<gblocks, 512>>>(th, yh, rowptr, adj, dinv2, n);

    // ---- layer 4: relu(yh+b3) @ W4 (64->32) -> th, fused gather+pool ----
    k_gemm_tch<64, 32, true, false><<<mblocks, 256>>>((const __half2*)yh, W4, b3, nullptr, (__half2*)th, n);
    k_gather32p_pool<<<gblocks, 512>>>(th, rowptr, adj, dinv2, b32, b4, pool, cnt, n);

    // ---- final FC ----
    k_final<<<1, 256>>>(pool, cnt, Wfc, bfc, out);
}

// round 17
// speedup vs baseline: 1.0474x; 1.0342x over previous
#include <cuda_runtime.h>
#include <cuda_fp16.h>

#define NMAX 100000
#define EMAX 1600000
#define NGRAPH 256
#define SCAN_B 256

// ---------------- static scratch (no allocation allowed) ----------------
__device__ int    g_degi[NMAX];
__device__ float  g_dinv[NMAX];
__device__ float  g_dinv2[NMAX];
__device__ int2   g_edge[EMAX];
__device__ int    g_rowptr[NMAX + 1];
__device__ int    g_tmp[NMAX];
__device__ int    g_partial[(NMAX + SCAN_B - 1) / SCAN_B + 1];
__device__ int    g_fill[NMAX];
__device__ float2 g_adj[EMAX];     // .x = src index bits, .y = norm weight
__device__ int    g_b32[NMAX];
__device__ __half g_xh[(size_t)NMAX * 64];    // fp16 input features
__device__ __half g_yh[(size_t)NMAX * 64];    // fp16 gather outputs (GEMM inputs)
__device__ __half g_th[(size_t)NMAX * 64];    // fp16 GEMM outputs (gather inputs)
__device__ __half g_h1h[(size_t)NMAX * 128];  // fp16 layer-1 activations
__device__ float  g_pool[NGRAPH * 32];
__device__ float  g_cnt[NGRAPH];
__device__ int    g_flag_ei;   // 1 = int64 data, 0 = int32 data
__device__ int    g_flag_b;
// Pre-packed weights in MMA fragment order (hi0,hi1,lo0,lo1).
__device__ uint4  g_Wp1[2048];   // 64x128
__device__ uint4  g_Wp2[2048];   // 128x64
__device__ uint4  g_Wp3[1024];   // 64x64
__device__ uint4  g_Wp4[512];    // 64x32

// ---------------- fp16 hi/lo split ----------------
__device__ __forceinline__ void splith(float x0, float x1, unsigned& hi, unsigned& lo) {
    __half h0 = __float2half_rn(x0);
    __half h1 = __float2half_rn(x1);
    __half l0 = __float2half_rn(x0 - __half2float(h0));
    __half l1 = __float2half_rn(x1 - __half2float(h1));
    hi = (unsigned)__half_as_ushort(h0) | ((unsigned)__half_as_ushort(h1) << 16);
    lo = (unsigned)__half_as_ushort(l0) | ((unsigned)__half_as_ushort(l1) << 16);
}

__device__ __forceinline__ void pack_w(const float* __restrict__ W, int KOUT,
                                       uint4* __restrict__ dst, int e, int NJ) {
    int l  = e & 31;
    int j  = (e >> 5) % NJ;
    int ks = e / (32 * NJ);
    int col = j * 8 + (l >> 2);
    int k0  = ks * 16 + (l & 3) * 2;
    float w00 = W[(k0 + 0) * KOUT + col];
    float w01 = W[(k0 + 1) * KOUT + col];
    float w10 = W[(k0 + 8) * KOUT + col];
    float w11 = W[(k0 + 9) * KOUT + col];
    uint4 p;
    splith(w00, w01, p.x, p.z);
    splith(w10, w11, p.y, p.w);
    dst[e] = p;
}

// ---------------- launch 1: zero + detect + x->fp16 + W pack ------------
__global__ void k_prep0(int* degi, int* fill, float* pool, float* cnt, int n,
                        const long long* __restrict__ ei, int cnt_ei,
                        const long long* __restrict__ batch, long long start_b, int cnt_b,
                        int* flag_ei, int* flag_b,
                        const float4* __restrict__ X, __half2* __restrict__ Xh,
                        int ZB, int CB,
                        const float* __restrict__ W1, const float* __restrict__ W2,
                        const float* __restrict__ W3, const float* __restrict__ W4,
                        uint4* Wp1, uint4* Wp2, uint4* Wp3, uint4* Wp4) {
    int bid = blockIdx.x;
    int tid = threadIdx.x;
    if (bid < 2) {
        const long long* p = bid ? batch : ei;
        long long start = bid ? start_b : 0;
        int count = bid ? cnt_b : cnt_ei;
        long long maxval = bid ? NGRAPH : n;
        int* flag = bid ? flag_b : flag_ei;
        __shared__ int bad;
        if (tid == 0) bad = 0;
        __syncthreads();
        for (int i = tid; i < count; i += blockDim.x) {
            long long v = p[start + i];
            if (v < 0 || v >= maxval) bad = 1;  // benign race
        }
        __syncthreads();
        if (tid == 0) *flag = bad ? 0 : 1;
    } else if (bid < 2 + ZB) {
        int i = (bid - 2) * 256 + tid;
        if (i < n) { degi[i] = 0; fill[i] = 0; }
        if (i < NGRAPH * 32) pool[i] = 0.f;
        if (i < NGRAPH) cnt[i] = 0.f;
    } else if (bid < 2 + ZB + CB) {
        int i = (bid - 2 - ZB) * 256 + tid;
        if (i < n * 16) {
            float4 v = __ldg(&X[i]);
            Xh[i * 2 + 0] = __floats2half2_rn(v.x, v.y);
            Xh[i * 2 + 1] = __floats2half2_rn(v.z, v.w);
        }
    } else {
        int idx = (bid - 2 - ZB - CB) * 256 + tid;   // [0, 5632)
        if (idx < 2048)      pack_w(W1, 128, Wp1, idx, 16);
        else if (idx < 4096) pack_w(W2, 64,  Wp2, idx - 2048, 8);
        else if (idx < 5120) pack_w(W3, 64,  Wp3, idx - 4096, 8);
        else if (idx < 5632) pack_w(W4, 32,  Wp4, idx - 5120, 4);
    }
}

// ---------------- launch 2: edge decode + degree ------------------------
__global__ void k_prep_edges(const void* __restrict__ ei, int2* __restrict__ edge,
                             int* degi, int E, int n, const int* __restrict__ flag) {
    int i = blockIdx.x * blockDim.x + threadIdx.x;
    if (i >= E) return;
    int s, d;
    if (*flag) {
        const long long* p = (const long long*)ei;
        s = (int)p[i];
        d = (int)p[(size_t)E + i];
    } else {
        const int* p = (const int*)ei;
        s = p[i];
        d = p[(size_t)E + i];
    }
    if ((unsigned)s >= (unsigned)n) s = 0;  // defensive: never trap
    if ((unsigned)d >= (unsigned)n) d = 0;
    edge[i] = make_int2(s, d);
    atomicAdd(&degi[d], 1);
}

// ---------------- launch 3: block scan + dinv ---------------------------
__global__ void k_scan1d(const int* __restrict__ degi, int* __restrict__ tmp,
                         int* __restrict__ partial, float* __restrict__ dinv,
                         float* __restrict__ dinv2, int n) {
    __shared__ int sh[SCAN_B];
    int t = threadIdx.x;
    int i = blockIdx.x * SCAN_B + t;
    int val = (i < n) ? degi[i] : 0;
    if (i < n) {
        float r = rsqrtf(1.0f + (float)val);
        dinv[i] = r;
        dinv2[i] = r * r;
    }
    sh[t] = val;
    __syncthreads();
    for (int off = 1; off < SCAN_B; off <<= 1) {
        int x = (t >= off) ? sh[t - off] : 0;
        __syncthreads();
        sh[t] += x;
        __syncthreads();
    }
    if (i < n) tmp[i] = sh[t] - val;              // exclusive within block
    if (t == SCAN_B - 1) partial[blockIdx.x] = sh[t];
}

__global__ void k_scan_part(int* partial, int nb) {
    __shared__ int sh[512];
    __shared__ int carry;
    int t = threadIdx.x;
    if (t == 0) carry = 0;
    __syncthreads();
    for (int base = 0; base < nb; base += 512) {
        int idx = base + t;
        int val = (idx < nb) ? partial[idx] : 0;
        sh[t] = val;
        __syncthreads();
        for (int off = 1; off < 512; off <<= 1) {
            int x = (t >= off) ? sh[t - off] : 0;
            __syncthreads();
            sh[t] += x;
            __syncthreads();
        }
        if (idx < nb) partial[idx] = sh[t] - val + carry;
        __syncthreads();
        if (t == 0) carry += sh[511];
        __syncthreads();
    }
}

__global__ void k_scan_add(const int* __restrict__ tmp, const int* __restrict__ partial,
                           int* __restrict__ rowptr, int n, int E) {
    int i = blockIdx.x * blockDim.x + threadIdx.x;
    if (i < n) rowptr[i] = tmp[i] + partial[i / SCAN_B];
    if (i == 0) rowptr[n] = E;
}

// ---------------- launch 6: CSR fill + batch convert --------------------
__global__ void k_fill_batch(const int2* __restrict__ edge, const int* __restrict__ rowptr,
                             int* __restrict__ fill, const float* __restrict__ dinv,
                             float2* __restrict__ adj, int E, int FB,
                             const void* __restrict__ batch, int* __restrict__ b32,
                             int n, const int* __restrict__ flag_b) {
    int bid = blockIdx.x;
    int tid = threadIdx.x;
    if (bid < FB) {
        int i = bid * 256 + tid;
        if (i >= E) return;
        int2 ed = edge[i];
        int pos = rowptr[ed.y] + atomicAdd(&fill[ed.y], 1);
        adj[pos] = make_float2(__int_as_float(ed.x), dinv[ed.x] * dinv[ed.y]);
    } else {
        int i = (bid - FB) * 256 + tid;
        if (i >= n) return;
        int b = (*flag_b) ? (int)((const long long*)batch)[i] : ((const int*)batch)[i];
        if ((unsigned)b >= (unsigned)NGRAPH) b = 0;
        b32[i] = b;
    }
}

// ---------------- paired-edge CSR gather (F=64, R14-proven) -------------
__global__ void __launch_bounds__(256)
k_gather64p(const __half* __restrict__ X, __half* __restrict__ Y,
            const int* __restrict__ rowptr, const float2* __restrict__ adj,
            const float* __restrict__ dinv2, int n) {
    int warp = (blockIdx.x * 256 + threadIdx.x) >> 5;
    int lane = threadIdx.x & 31;
    int hw = lane >> 4;      // half-warp id (edge parity)
    int hl = lane & 15;      // lane within half: features [4*hl, 4*hl+4)
    if (warp >= n) return;
    int start = __ldg(&rowptr[warp]);
    int end   = __ldg(&rowptr[warp + 1]);
    float a0 = 0.f, a1 = 0.f, a2 = 0.f, a3 = 0.f;
    if (hw == 0) {  // self-loop term on low half only
        float sw = __ldg(&dinv2[warp]);
        uint2 u = __ldg((const uint2*)(X + (size_t)warp * 64) + hl);
        float2 fa = __half22float2(*(__half2*)&u.x);
        float2 fb = __half22float2(*(__half2*)&u.y);
        a0 = fa.x * sw; a1 = fa.y * sw; a2 = fb.x * sw; a3 = fb.y * sw;
    }
    for (int i = start; i < end; i += 2) {
        int e = i + hw;
        if (e < end) {
            float2 ae = __ldg(&adj[e]);
            int src = __float_as_int(ae.x);
            float w = ae.y;
            uint2 u = __ldg((const uint2*)(X + (size_t)src * 64) + hl);
            float2 fa = __half22float2(*(__half2*)&u.x);
            float2 fb = __half22float2(*(__half2*)&u.y);
            a0 += fa.x * w; a1 += fa.y * w; a2 += fb.x * w; a3 += fb.y * w;
        }
    }
    a0 += __shfl_down_sync(0xffffffffu, a0, 16);
    a1 += __shfl_down_sync(0xffffffffu, a1, 16);
    a2 += __shfl_down_sync(0xffffffffu, a2, 16);
    a3 += __shfl_down_sync(0xffffffffu, a3, 16);
    if (hw == 0) {
        uint2 o;
        *(__half2*)&o.x = __floats2half2_rn(a0, a1);
        *(__half2*)&o.y = __floats2half2_rn(a2, a3);
        ((uint2*)(Y + (size_t)warp * 64))[hl] = o;
    }
}

// Paired-edge F=32 gather fused with bias+relu+mean-pool (R14-proven).
__global__ void __launch_bounds__(256)
k_gather32p_pool(const __half* __restrict__ X,
                 const int* __restrict__ rowptr, const float2* __restrict__ adj,
                 const float* __restrict__ dinv2, const int* __restrict__ batch,
                 const float* __restrict__ b4, float* __restrict__ pool,
                 float* __restrict__ cnt, int n) {
    int warp = (blockIdx.x * 256 + threadIdx.x) >> 5;
    int lane = threadIdx.x & 31;
    int hw = lane >> 4;
    int hl = lane & 15;
    if (warp >= n) return;
    int start = __ldg(&rowptr[warp]);
    int end   = __ldg(&rowptr[warp + 1]);
    float a0 = 0.f, a1 = 0.f;
    if (hw == 0) {
        float sw = __ldg(&dinv2[warp]);
        float2 f = __half22float2(__ldg((const __half2*)(X + (size_t)warp * 32) + hl));
        a0 = f.x * sw; a1 = f.y * sw;
    }
    for (int i = start; i < end; i += 2) {
        int e = i + hw;
        if (e < end) {
            float2 ae = __ldg(&adj[e]);
            int src = __float_as_int(ae.x);
            float w = ae.y;
            float2 f = __half22float2(__ldg((const __half2*)(X + (size_t)src * 32) + hl));
            a0 += f.x * w; a1 += f.y * w;
        }
    }
    a0 += __shfl_down_sync(0xffffffffu, a0, 16);
    a1 += __shfl_down_sync(0xffffffffu, a1, 16);
    if (hw == 0) {
        int b = __ldg(&batch[warp]);
        float v0 = fmaxf(a0 + __ldg(&b4[2 * hl]),     0.f);
        float v1 = fmaxf(a1 + __ldg(&b4[2 * hl + 1]), 0.f);
        atomicAdd(&pool[b * 32 + 2 * hl],     v0);
        atomicAdd(&pool[b * 32 + 2 * hl + 1], v1);
        if (hl == 0) atomicAdd(&cnt[b], 1.0f);
    }
}

// ---------------- tensor-core GEMM: fp16 A (exact), pre-packed W --------
__device__ __forceinline__ void mma16816h(float* c, const unsigned* a,
                                          unsigned b0, unsigned b1) {
    asm volatile("mma.sync.aligned.m16n8k16.row.col.f32.f16.f16.f32 "
                 "{%0,%1,%2,%3}, {%4,%5,%6,%7}, {%8,%9}, {%0,%1,%2,%3};"
                 : "+f"(c[0]), "+f"(c[1]), "+f"(c[2]), "+f"(c[3])
                 : "r"(a[0]), "r"(a[1]), "r"(a[2]), "r"(a[3]), "r"(b0), "r"(b1));
}

template <int KIN, int KOUT, bool INACT, bool OUTACT>
__global__ void __launch_bounds__(256)
k_gemm_tch(const __half2* __restrict__ X, const uint4* __restrict__ Wg,
           const float* __restrict__ bin, const float* __restrict__ bout,
           __half2* __restrict__ Y, int n) {
    constexpr int KS = KIN / 16;   // k-steps
    constexpr int NJ = KOUT / 8;   // n-tiles
    __shared__ uint4 Wp[KS * NJ * 32];    // (hi0,hi1,lo0,lo1) fragment-order
    __shared__ __half2 binh[KIN / 2];
    __shared__ float bouts[KOUT];
    int tid = threadIdx.x;
    int lane = tid & 31;
    int warp = tid >> 5;
    int g = lane >> 2;      // groupID (0-7)
    int tg = lane & 3;      // thread-in-group

    if (INACT)  for (int i = tid; i < KIN / 2; i += 256)
        binh[i] = __floats2half2_rn(bin[2 * i], bin[2 * i + 1]);
    if (OUTACT) for (int i = tid; i < KOUT; i += 256) bouts[i] = bout[i];
    for (int e = tid; e < KS * NJ * 32; e += 256) Wp[e] = __ldg(&Wg[e]);
    __syncthreads();

    int rowBase = blockIdx.x * 128 + warp * 16;
    int r0 = rowBase + g;
    int r1 = r0 + 8;
    bool v0 = (r0 < n), v1 = (r1 < n);
    const __half2* xr0 = X + (size_t)r0 * (KIN / 2);
    const __half2* xr1 = X + (size_t)r1 * (KIN / 2);
    const __half2 z2 = __floats2half2_rn(0.f, 0.f);

    unsigned a[KS * 4];
#pragma unroll
    for (int ks = 0; ks < KS; ks++) {
        int c2 = (ks * 16 + tg * 2) / 2;   // half2 index
        __half2 h00 = v0 ? xr0[c2]     : z2;
        __half2 h01 = v0 ? xr0[c2 + 4] : z2;
        __half2 h10 = v1 ? xr1[c2]     : z2;
        __half2 h11 = v1 ? xr1[c2 + 4] : z2;
        if (INACT) {
            h00 = __hmax2(__hadd2(h00, binh[c2]),     z2);
            h01 = __hmax2(__hadd2(h01, binh[c2 + 4]), z2);
            h10 = __hmax2(__hadd2(h10, binh[c2]),     z2);
            h11 = __hmax2(__hadd2(h11, binh[c2 + 4]), z2);
        }
        a[ks * 4 + 0] = *reinterpret_cast<unsigned*>(&h00);
        a[ks * 4 + 1] = *reinterpret_cast<unsigned*>(&h10);
        a[ks * 4 + 2] = *reinterpret_cast<unsigned*>(&h01);
        a[ks * 4 + 3] = *reinterpret_cast<unsigned*>(&h11);
    }

#pragma unroll
    for (int j = 0; j < NJ; j++) {
        float c[4] = {0.f, 0.f, 0.f, 0.f};
#pragma unroll
        for (int ks = 0; ks < KS; ks++) {
            uint4 wp = Wp[(ks * NJ + j) * 32 + lane];
            mma16816h(c, &a[ks * 4], wp.x, wp.y);   // A * Whi
            mma16816h(c, &a[ks * 4], wp.z, wp.w);   // A * Wlo
        }
        int col0 = j * 8 + tg * 2;
        if (OUTACT) {
            c[0] = fmaxf(c[0] + bouts[col0],     0.f);
            c[1] = fmaxf(c[1] + bouts[col0 + 1], 0.f);
            c[2] = fmaxf(c[2] + bouts[col0],     0.f);
            c[3] = fmaxf(c[3] + bouts[col0 + 1], 0.f);
        }
        if (v0) Y[((size_t)r0 * KOUT + col0) / 2] = __floats2half2_rn(c[0], c[1]);
        if (v1) Y[((size_t)r1 * KOUT + col0) / 2] = __floats2half2_rn(c[2], c[3]);
    }
}

// ---------------- final FC ----------------
__global__ void k_final(const float* __restrict__ pool, const float* __restrict__ cnt,
                        const float* __restrict__ Wfc, const float* __restrict__ bfc,
                        float* __restrict__ out) {
    int g = threadIdx.x;
    if (g >= NGRAPH) return;
    float s = 0.f;
#pragma unroll
    for (int f = 0; f < 32; f++) s += pool[g * 32 + f] * Wfc[f];
    out[g] = s / fmaxf(cnt[g], 1.0f) + bfc[0];
}

// ---------------- host ----------------
extern "C" void kernel_launch(void* const* d_in, const int* in_sizes, int n_in,
                              void* d_out, int out_size) {
    const float* x     = (const float*)d_in[0];
    const void*  ei    = d_in[1];
    const void*  batch = d_in[2];

    int base = -1;
    for (int i = 3; i + 9 < n_in; i++) {
        if (in_sizes[i] == 8192 && in_sizes[i + 1] == 128 &&
            in_sizes[i + 2] == 8192 && in_sizes[i + 3] == 64 &&
            in_sizes[i + 4] == 4096 && in_sizes[i + 5] == 64 &&
            in_sizes[i + 6] == 2048 && in_sizes[i + 7] == 32 &&
            in_sizes[i + 8] == 32 && in_sizes[i + 9] == 1) {
            base = i;
            break;
        }
    }
    if (base < 0) base = (n_in >= 14) ? 4 : 3;  // fallback

    const float* W1  = (const float*)d_in[base + 0];
    const float* b1  = (const float*)d_in[base + 1];
    const float* W2  = (const float*)d_in[base + 2];
    const float* b2  = (const float*)d_in[base + 3];
    const float* W3  = (const float*)d_in[base + 4];
    const float* b3  = (const float*)d_in[base + 5];
    const float* W4  = (const float*)d_in[base + 6];
    const float* b4  = (const float*)d_in[base + 7];
    const float* Wfc = (const float*)d_in[base + 8];
    const float* bfc = (const float*)d_in[base + 9];
    float* out = (float*)d_out;

    int n = in_sizes[0] / 64;
    int E = in_sizes[1] / 2;

    float *dinv, *dinv2, *pool, *cnt;
    __half *xh, *yh, *th, *h1h;
    float2* adj;
    int2* edge;
    uint4 *Wp1, *Wp2, *Wp3, *Wp4;
    int *degi, *rowptr, *tmp, *partial, *fill, *b32, *flag_ei, *flag_b;
    cudaGetSymbolAddress((void**)&degi,    g_degi);
    cudaGetSymbolAddress((void**)&dinv,    g_dinv);
    cudaGetSymbolAddress((void**)&dinv2,   g_dinv2);
    cudaGetSymbolAddress((void**)&edge,    g_edge);
    cudaGetSymbolAddress((void**)&rowptr,  g_rowptr);
    cudaGetSymbolAddress((void**)&tmp,     g_tmp);
    cudaGetSymbolAddress((void**)&partial, g_partial);
    cudaGetSymbolAddress((void**)&fill,    g_fill);
    cudaGetSymbolAddress((void**)&adj,     g_adj);
    cudaGetSymbolAddress((void**)&b32,     g_b32);
    cudaGetSymbolAddress((void**)&xh,      g_xh);
    cudaGetSymbolAddress((void**)&yh,      g_yh);
    cudaGetSymbolAddress((void**)&th,      g_th);
    cudaGetSymbolAddress((void**)&h1h,     g_h1h);
    cudaGetSymbolAddress((void**)&pool,    g_pool);
    cudaGetSymbolAddress((void**)&cnt,     g_cnt);
    cudaGetSymbolAddress((void**)&flag_ei, g_flag_ei);
    cudaGetSymbolAddress((void**)&flag_b,  g_flag_b);
    cudaGetSymbolAddress((void**)&Wp1,     g_Wp1);
    cudaGetSymbolAddress((void**)&Wp2,     g_Wp2);
    cudaGetSymbolAddress((void**)&Wp3,     g_Wp3);
    cudaGetSymbolAddress((void**)&Wp4,     g_Wp4);

    const int TB = 256;
    auto cdiv = [](long long a, long long b) { return (int)((a + b - 1) / b); };
    int nb = cdiv(n, SCAN_B);

    // ---- prep (6 launches) ----
    {
        int cnt_ei = (E / 2 < 4096) ? E / 2 : 4096;
        int cnt_b = (n / 2 < 4096) ? n / 2 : 4096;
        long long start_b = (long long)(n / 2) - cnt_b;
        int ZB = cdiv(n, TB);
        int CB = cdiv((long long)n * 16, TB);
        int WB = cdiv(5632, TB);
        k_prep0<<<2 + ZB + CB + WB, TB>>>(degi, fill, pool, cnt, n,
                                          (const long long*)ei, cnt_ei,
                                          (const long long*)batch, start_b, cnt_b,
                                          flag_ei, flag_b,
                                          (const float4*)x, (__half2*)xh, ZB, CB,
                                          W1, W2, W3, W4, Wp1, Wp2, Wp3, Wp4);
    }
    k_prep_edges<<<cdiv(E, TB), TB>>>(ei, edge, degi, E, n, flag_ei);
    k_scan1d<<<nb, SCAN_B>>>(degi, tmp, partial, dinv, dinv2, n);
    k_scan_part<<<1, 512>>>(partial, nb);
    k_scan_add<<<cdiv(n, TB), TB>>>(tmp, partial, rowptr, n, E);
    {
        int FB = cdiv(E, TB);
        int BB = cdiv(n, TB);
        k_fill_batch<<<FB + BB, TB>>>(edge, rowptr, fill, dinv, adj, E, FB,
                                      batch, b32, n, flag_b);
    }

    int gblocks = cdiv((long long)n * 32, TB);  // one warp per node
    int mblocks = cdiv(n, 128);                 // 128 rows per GEMM block

    // ---- layer 1: aggregate xh (64) -> yh, GEMM 64->128 (+b1+relu) -> h1h ----
    k_gather64p<<<gblocks, TB>>>(xh, yh, rowptr, adj, dinv2, n);
    k_gemm_tch<64, 128, false, true><<<mblocks, 256>>>((const __half2*)yh, Wp1, nullptr, b1, (__half2*)h1h, n);

    // ---- layer 2: GEMM 128->64 -> th, aggregate -> yh ----
    k_gemm_tch<128, 64, false, false><<<mblocks, 256>>>((const __half2*)h1h, Wp2, nullptr, nullptr, (__half2*)th, n);
    k_gather64p<<<gblocks, TB>>>(th, yh, rowptr, adj, dinv2, n);

    // ---- layer 3: relu(yh+b2) @ W3 (64->64) -> th, aggregate -> yh ----
    k_gemm_tch<64, 64, true, false><<<mblocks, 256>>>((const __half2*)yh, Wp3, b2, nullptr, (__half2*)th, n);
    k_gather64p<<<gblocks, TB>>>(th, yh, rowptr, adj, dinv2, n);

    // ---- layer 4: relu(yh+b3) @ W4 (64->32) -> th, fused gather+pool ----
    k_gemm_tch<64, 32, true, false><<<mblocks, 256>>>((const __half2*)yh, Wp4, b3, nullptr, (__half2*)th, n);
    k_gather32p_pool<<<gblocks, TB>>>(th, rowptr, adj, dinv2, b32, b4, pool, cnt, n);

    // ---- final FC ----
    k_final<<<1, 256>>>(pool, cnt, Wfc, bfc, out);
}